// round 1
// baseline (speedup 1.0000x reference)
#include <cuda_runtime.h>
#include <stdint.h>

// Binarized depthwise 3x3 conv, stride 1, SAME padding.
// x: (16,112,112,256) NHWC fp32; kernel: (3,3,256,1) fp32.
// out[n,h,w,c] = sum over valid taps of sign(x)*sign(k), sign(0)=+1.
//
// Per tap per channel: product = as_float((as_int(x)&0x80000000) ^ kp)
// where kp holds bits of +-1.0f from the kernel sign. Invalid rows get kp=0,
// which makes the product +-0.0f (a no-op under FADD) -> branch-free rows.

#define NN 16
#define HH 112
#define WW 112
#define CC 256

__device__ __forceinline__ void tap(float4& acc, const float4 xv, const uint4 kp) {
    acc.x += __int_as_float((__float_as_uint(xv.x) & 0x80000000u) ^ kp.x);
    acc.y += __int_as_float((__float_as_uint(xv.y) & 0x80000000u) ^ kp.y);
    acc.z += __int_as_float((__float_as_uint(xv.z) & 0x80000000u) ^ kp.z);
    acc.w += __int_as_float((__float_as_uint(xv.w) & 0x80000000u) ^ kp.w);
}

__device__ __forceinline__ float4 ldcol(const float* __restrict__ r, int col) {
    return *reinterpret_cast<const float4*>(r + (size_t)col * CC);
}

__global__ __launch_bounds__(256, 2)
void bconv_kernel(const float* __restrict__ x,
                  const float* __restrict__ k,
                  float* __restrict__ out) {
    const int h = blockIdx.x;
    const int n = blockIdx.y;
    const int t = threadIdx.x;
    const int c4 = t & 63;          // which float4 of the 256 channels
    const int strip = t >> 6;       // 0..3, each strip covers 28 w positions
    const int c0 = c4 * 4;

    const bool hasT = (h > 0);
    const bool hasB = (h < HH - 1);

    // Kernel signs as bits of +-1.0f; zero out taps of missing rows.
    uint4 kp[3][3];
#pragma unroll
    for (int kh = 0; kh < 3; ++kh) {
        const bool rowvalid = (kh == 0) ? hasT : ((kh == 2) ? hasB : true);
#pragma unroll
        for (int kw = 0; kw < 3; ++kw) {
            const float4 kv = *reinterpret_cast<const float4*>(k + (kh * 3 + kw) * CC + c0);
            uint4 v;
            v.x = (kv.x >= 0.0f) ? 0x3F800000u : 0xBF800000u;
            v.y = (kv.y >= 0.0f) ? 0x3F800000u : 0xBF800000u;
            v.z = (kv.z >= 0.0f) ? 0x3F800000u : 0xBF800000u;
            v.w = (kv.w >= 0.0f) ? 0x3F800000u : 0xBF800000u;
            if (!rowvalid) { v.x = 0u; v.y = 0u; v.z = 0u; v.w = 0u; }
            kp[kh][kw] = v;
        }
    }

    const int hm = hasT ? h - 1 : h;   // clamped (contribution zeroed via kp)
    const int hp = hasB ? h + 1 : h;
    const float* r0 = x + (((size_t)n * HH + hm) * WW) * CC + c0;
    const float* r1 = x + (((size_t)n * HH + h ) * WW) * CC + c0;
    const float* r2 = x + (((size_t)n * HH + hp) * WW) * CC + c0;
    float*       o  = out + (((size_t)n * HH + h) * WW) * CC + c0;

    const int ws = strip * (WW / 4);
    const int we = ws + (WW / 4);

    // Sliding register window: A = col w-1, B = col w, C = col w+1 (3 rows each).
    float4 A0, A1, A2, B0, B1, B2, C0, C1, C2;
    int w = ws;

    if (ws == 0) {
        // Peeled w=0: no left column.
        B0 = ldcol(r0, 0); B1 = ldcol(r1, 0); B2 = ldcol(r2, 0);
        C0 = ldcol(r0, 1); C1 = ldcol(r1, 1); C2 = ldcol(r2, 1);
        float4 acc = make_float4(0.f, 0.f, 0.f, 0.f);
        tap(acc, B0, kp[0][1]); tap(acc, B1, kp[1][1]); tap(acc, B2, kp[2][1]);
        tap(acc, C0, kp[0][2]); tap(acc, C1, kp[1][2]); tap(acc, C2, kp[2][2]);
        *reinterpret_cast<float4*>(o) = acc;
        A0 = B0; A1 = B1; A2 = B2;
        B0 = C0; B1 = C1; B2 = C2;
        w = 1;
    } else {
        A0 = ldcol(r0, ws - 1); A1 = ldcol(r1, ws - 1); A2 = ldcol(r2, ws - 1);
        B0 = ldcol(r0, ws);     B1 = ldcol(r1, ws);     B2 = ldcol(r2, ws);
    }

    const int wlast = (we == WW) ? WW - 1 : we;  // last strip peels w=111

#pragma unroll 2
    for (; w < wlast; ++w) {
        C0 = ldcol(r0, w + 1); C1 = ldcol(r1, w + 1); C2 = ldcol(r2, w + 1);
        float4 acc = make_float4(0.f, 0.f, 0.f, 0.f);
        tap(acc, A0, kp[0][0]); tap(acc, A1, kp[1][0]); tap(acc, A2, kp[2][0]);
        tap(acc, B0, kp[0][1]); tap(acc, B1, kp[1][1]); tap(acc, B2, kp[2][1]);
        tap(acc, C0, kp[0][2]); tap(acc, C1, kp[1][2]); tap(acc, C2, kp[2][2]);
        *reinterpret_cast<float4*>(o + (size_t)w * CC) = acc;
        A0 = B0; A1 = B1; A2 = B2;
        B0 = C0; B1 = C1; B2 = C2;
    }

    if (we == WW) {
        // Peeled w=W-1: no right column.
        float4 acc = make_float4(0.f, 0.f, 0.f, 0.f);
        tap(acc, A0, kp[0][0]); tap(acc, A1, kp[1][0]); tap(acc, A2, kp[2][0]);
        tap(acc, B0, kp[0][1]); tap(acc, B1, kp[1][1]); tap(acc, B2, kp[2][1]);
        *reinterpret_cast<float4*>(o + (size_t)(WW - 1) * CC) = acc;
    }
}

extern "C" void kernel_launch(void* const* d_in, const int* in_sizes, int n_in,
                              void* d_out, int out_size) {
    const float* x = (const float*)d_in[0];
    const float* k = (const float*)d_in[1];
    float* out = (float*)d_out;
    dim3 grid(HH, NN);
    bconv_kernel<<<grid, 256>>>(x, k, out);
}

// round 2
// speedup vs baseline: 1.2478x; 1.2478x over previous
#include <cuda_runtime.h>
#include <stdint.h>

// Binarized depthwise 3x3 conv, stride 1, SAME. x:(16,112,112,256) NHWC fp32,
// kernel:(3,3,256,1). out = sum of sign(x)*sign(k) over valid taps.
//
// bf16x2 formulation: pack 2 channels' sign info into one register (PRMT of
// the two fp32 high halves). Per tap: one LOP3 ((t & 0x80008000) ^ kp) gives
// a bf16x2 of +-1.0 (or +-0.0 for zeroed border-row kp), accumulated with
// add.rn.bf16x2 (exact: |sum| <= 9). Unpack to fp32 is shift/mask (exact).
//
// Streaming column recurrence (no 3x3 register window):
//   column c -> q0,q1,q2 (column-sums against kw=0,1,2 taps)
//   out[c-1] = A + q2 ; A = B + q1 ; B = q0

#define NN 16
#define HH 112
#define WW 112
#define CC 256

__device__ __forceinline__ uint32_t badd(uint32_t a, uint32_t b) {
    uint32_t r;
    asm("add.rn.bf16x2 %0, %1, %2;" : "=r"(r) : "r"(a), "r"(b));
    return r;
}

#define TAPP(t, kp) ((((t) & 0x80008000u)) ^ (kp))

__device__ __forceinline__ float4 ldcol(const float* __restrict__ r, int col) {
    return *reinterpret_cast<const float4*>(r + (size_t)col * CC);
}

__global__ __launch_bounds__(256, 4)
void bconv_kernel(const float* __restrict__ x,
                  const float* __restrict__ k,
                  float* __restrict__ out) {
    const int h = blockIdx.x;
    const int n = blockIdx.y;
    const int t = threadIdx.x;
    const int c4 = t & 63;        // which float4 of 256 channels
    const int strip = t >> 6;     // 4 strips of 28 output columns
    const int c0 = c4 * 4;

    const bool hasT = (h > 0);
    const bool hasB = (h < HH - 1);

    // kp[kh][kw][half]: bf16x2 of per-channel +-1.0 kernel signs; 0 for
    // missing border rows (adds +-0.0 -> no-op).
    uint32_t kp[3][3][2];
#pragma unroll
    for (int kh = 0; kh < 3; ++kh) {
        const bool rv = (kh == 0) ? hasT : ((kh == 2) ? hasB : true);
#pragma unroll
        for (int kw = 0; kw < 3; ++kw) {
            const float4 kv = *reinterpret_cast<const float4*>(k + (kh * 3 + kw) * CC + c0);
            uint32_t s0 = (kv.x >= 0.0f) ? 0x3F80u : 0xBF80u;
            uint32_t s1 = (kv.y >= 0.0f) ? 0x3F80u : 0xBF80u;
            uint32_t s2 = (kv.z >= 0.0f) ? 0x3F80u : 0xBF80u;
            uint32_t s3 = (kv.w >= 0.0f) ? 0x3F80u : 0xBF80u;
            kp[kh][kw][0] = rv ? (s0 | (s1 << 16)) : 0u;
            kp[kh][kw][1] = rv ? (s2 | (s3 << 16)) : 0u;
        }
    }

    const int hm = hasT ? h - 1 : h;   // clamped; contribution zeroed via kp
    const int hp = hasB ? h + 1 : h;
    const float* r0 = x + (((size_t)n * HH + hm) * WW) * CC + c0;
    const float* r1 = x + (((size_t)n * HH + h ) * WW) * CC + c0;
    const float* r2 = x + (((size_t)n * HH + hp) * WW) * CC + c0;
    float*       o  = out + (((size_t)n * HH + h) * WW) * CC + c0;

    const int ws = strip * (WW / 4);
    const int we = ws + (WW / 4);
    const int cend = (we == WW) ? WW - 1 : we;

    uint32_t A0 = 0, A1 = 0, B0 = 0, B1 = 0;

    int c = (ws == 0) ? 0 : ws - 1;
#pragma unroll 2
    for (; c <= cend; ++c) {
        const float4 v0 = ldcol(r0, c);
        const float4 v1 = ldcol(r1, c);
        const float4 v2 = ldcol(r2, c);
        // pack fp32 pairs -> bf16x2 (high halves): low = even ch, high = odd ch
        const uint32_t t0a = __byte_perm(__float_as_uint(v0.x), __float_as_uint(v0.y), 0x7632);
        const uint32_t t0b = __byte_perm(__float_as_uint(v0.z), __float_as_uint(v0.w), 0x7632);
        const uint32_t t1a = __byte_perm(__float_as_uint(v1.x), __float_as_uint(v1.y), 0x7632);
        const uint32_t t1b = __byte_perm(__float_as_uint(v1.z), __float_as_uint(v1.w), 0x7632);
        const uint32_t t2a = __byte_perm(__float_as_uint(v2.x), __float_as_uint(v2.y), 0x7632);
        const uint32_t t2b = __byte_perm(__float_as_uint(v2.z), __float_as_uint(v2.w), 0x7632);

        const uint32_t q0a = badd(badd(TAPP(t0a, kp[0][0][0]), TAPP(t1a, kp[1][0][0])), TAPP(t2a, kp[2][0][0]));
        const uint32_t q0b = badd(badd(TAPP(t0b, kp[0][0][1]), TAPP(t1b, kp[1][0][1])), TAPP(t2b, kp[2][0][1]));
        const uint32_t q1a = badd(badd(TAPP(t0a, kp[0][1][0]), TAPP(t1a, kp[1][1][0])), TAPP(t2a, kp[2][1][0]));
        const uint32_t q1b = badd(badd(TAPP(t0b, kp[0][1][1]), TAPP(t1b, kp[1][1][1])), TAPP(t2b, kp[2][1][1]));
        const uint32_t q2a = badd(badd(TAPP(t0a, kp[0][2][0]), TAPP(t1a, kp[1][2][0])), TAPP(t2a, kp[2][2][0]));
        const uint32_t q2b = badd(badd(TAPP(t0b, kp[0][2][1]), TAPP(t1b, kp[1][2][1])), TAPP(t2b, kp[2][2][1]));

        if (c > ws) {  // completes out[c-1] (warp-uniform predicate)
            const uint32_t oa = badd(A0, q2a);
            const uint32_t ob = badd(A1, q2b);
            float4 o4;
            o4.x = __uint_as_float(oa << 16);
            o4.y = __uint_as_float(oa & 0xFFFF0000u);
            o4.z = __uint_as_float(ob << 16);
            o4.w = __uint_as_float(ob & 0xFFFF0000u);
            *reinterpret_cast<float4*>(o + (size_t)(c - 1) * CC) = o4;
        }
        A0 = badd(B0, q1a); A1 = badd(B1, q1b);
        B0 = q0a;           B1 = q0b;
    }

    if (we == WW) {  // right border: out[111] = q0(110) + q1(111)
        float4 o4;
        o4.x = __uint_as_float(A0 << 16);
        o4.y = __uint_as_float(A0 & 0xFFFF0000u);
        o4.z = __uint_as_float(A1 << 16);
        o4.w = __uint_as_float(A1 & 0xFFFF0000u);
        *reinterpret_cast<float4*>(o + (size_t)(WW - 1) * CC) = o4;
    }
}

extern "C" void kernel_launch(void* const* d_in, const int* in_sizes, int n_in,
                              void* d_out, int out_size) {
    const float* x = (const float*)d_in[0];
    const float* k = (const float*)d_in[1];
    float* out = (float*)d_out;
    dim3 grid(HH, NN);
    bconv_kernel<<<grid, 256>>>(x, k, out);
}

// round 3
// speedup vs baseline: 1.2609x; 1.0105x over previous
#include <cuda_runtime.h>
#include <stdint.h>

// Binarized depthwise 3x3 conv, stride 1, SAME. x:(16,112,112,256) NHWC fp32,
// kernel:(3,3,256,1). out = sum of sign(x)*sign(k) over valid taps.
//
// bf16x2 math: pack 2 channels' fp32 high-halves into one reg (PRMT); per tap
// one LOP3 ((t & 0x80008000) ^ kp) yields bf16x2 of +-1.0 (or +-0.0 for
// zeroed border-row kp); accumulate with add.rn.bf16x2 (exact, |sum|<=9).
//
// 2 channels per thread, 128-thread block = one (n,h) output row.
// Streaming column recurrence: out[c-1] = A + q2(c); A = B + q1(c); B = q0(c).

#define NN 16
#define HH 112
#define WW 112
#define CC 256

__device__ __forceinline__ uint32_t badd(uint32_t a, uint32_t b) {
    uint32_t r;
    asm("add.rn.bf16x2 %0, %1, %2;" : "=r"(r) : "r"(a), "r"(b));
    return r;
}

#define TAPP(t, kp) ((((t) & 0x80008000u)) ^ (kp))

__global__ __launch_bounds__(128, 11)
void bconv_kernel(const float* __restrict__ x,
                  const float* __restrict__ k,
                  float* __restrict__ out) {
    const int h = blockIdx.x;
    const int n = blockIdx.y;
    const int t = threadIdx.x;          // channel pair 0..127
    const int c0 = t * 2;

    const bool hasT = (h > 0);
    const bool hasB = (h < HH - 1);

    // kp[kh][kw]: bf16x2 of per-channel +-1.0 kernel signs; 0 for missing rows.
    uint32_t kp[3][3];
#pragma unroll
    for (int kh = 0; kh < 3; ++kh) {
        const bool rv = (kh == 0) ? hasT : ((kh == 2) ? hasB : true);
#pragma unroll
        for (int kw = 0; kw < 3; ++kw) {
            const float2 kv = *reinterpret_cast<const float2*>(k + (kh * 3 + kw) * CC + c0);
            uint32_t s0 = (kv.x >= 0.0f) ? 0x3F80u : 0xBF80u;
            uint32_t s1 = (kv.y >= 0.0f) ? 0x3F80u : 0xBF80u;
            kp[kh][kw] = rv ? (s0 | (s1 << 16)) : 0u;
        }
    }

    const int hm = hasT ? h - 1 : h;    // clamped; contribution zeroed via kp
    const int hp = hasB ? h + 1 : h;
    const float* r0 = x + (((size_t)n * HH + hm) * WW) * CC + c0;
    const float* r1 = x + (((size_t)n * HH + h ) * WW) * CC + c0;
    const float* r2 = x + (((size_t)n * HH + hp) * WW) * CC + c0;
    float*       o  = out + (((size_t)n * HH + h) * WW) * CC + c0;

    uint32_t A = 0, B = 0;

#pragma unroll 4
    for (int c = 0; c < WW; ++c) {
        const float2 v0 = *reinterpret_cast<const float2*>(r0 + (size_t)c * CC);
        const float2 v1 = *reinterpret_cast<const float2*>(r1 + (size_t)c * CC);
        const float2 v2 = *reinterpret_cast<const float2*>(r2 + (size_t)c * CC);
        const uint32_t t0 = __byte_perm(__float_as_uint(v0.x), __float_as_uint(v0.y), 0x7632);
        const uint32_t t1 = __byte_perm(__float_as_uint(v1.x), __float_as_uint(v1.y), 0x7632);
        const uint32_t t2 = __byte_perm(__float_as_uint(v2.x), __float_as_uint(v2.y), 0x7632);

        const uint32_t q0 = badd(badd(TAPP(t0, kp[0][0]), TAPP(t1, kp[1][0])), TAPP(t2, kp[2][0]));
        const uint32_t q1 = badd(badd(TAPP(t0, kp[0][1]), TAPP(t1, kp[1][1])), TAPP(t2, kp[2][1]));
        const uint32_t q2 = badd(badd(TAPP(t0, kp[0][2]), TAPP(t1, kp[1][2])), TAPP(t2, kp[2][2]));

        if (c > 0) {  // completes out[c-1] (uniform predicate)
            const uint32_t ov = badd(A, q2);
            float2 o2;
            o2.x = __uint_as_float(ov << 16);
            o2.y = __uint_as_float(ov & 0xFFFF0000u);
            *reinterpret_cast<float2*>(o + (size_t)(c - 1) * CC) = o2;
        }
        A = badd(B, q1);
        B = q0;
    }

    // Right border: out[111] = q0(110) + q1(111) = A after the loop.
    {
        float2 o2;
        o2.x = __uint_as_float(A << 16);
        o2.y = __uint_as_float(A & 0xFFFF0000u);
        *reinterpret_cast<float2*>(o + (size_t)(WW - 1) * CC) = o2;
    }
}

extern "C" void kernel_launch(void* const* d_in, const int* in_sizes, int n_in,
                              void* d_out, int out_size) {
    const float* x = (const float*)d_in[0];
    const float* k = (const float*)d_in[1];
    float* out = (float*)d_out;
    dim3 grid(HH, NN);
    bconv_kernel<<<grid, 128>>>(x, k, out);
}